// round 17
// baseline (speedup 1.0000x reference)
#include <cuda_runtime.h>
#include <cuda_fp16.h>
#include <cstdint>
#include <cstddef>

#define N_NODES 20000
#define MPAD    20096
#define F_IN  256
#define F_HID 512
#define F_OUT 256
#define ELL   128

// ---------------- scratch (no allocations allowed) ----------------
__device__ int      g_cnt[N_NODES];
__device__ int      g_esrc[(size_t)N_NODES * ELL];
__device__ int      g_is64;
__device__ uint32_t g_Xh[(size_t)N_NODES * (F_IN / 2)];    // X as half2-packed fp16
__device__ uint32_t g_P1h[(size_t)MPAD * (F_IN  / 2)];
__device__ uint32_t g_P1l[(size_t)MPAD * (F_IN  / 2)];
__device__ uint32_t g_H1h[(size_t)MPAD * (F_HID / 2)];
__device__ uint32_t g_H1l[(size_t)MPAD * (F_HID / 2)];
__device__ uint32_t g_W1h[(size_t)(F_IN  / 2) * F_HID];
__device__ uint32_t g_W1l[(size_t)(F_IN  / 2) * F_HID];
__device__ uint32_t g_W2h[(size_t)(F_HID / 2) * F_OUT];
__device__ uint32_t g_W2l[(size_t)(F_HID / 2) * F_OUT];
__device__ uint32_t g_Th[(size_t)N_NODES * (F_OUT / 2)];   // GEMM2 out, half2-packed fp16

// ---------------- helpers ----------------
__device__ __forceinline__ int load_idx(const void* e, long long pos, int is64) {
    if (is64) return (int)((const long long*)e)[pos];
    return ((const int*)e)[pos];
}

__device__ __forceinline__ void splitf2(float x, float y, uint32_t& hi, uint32_t& lo) {
    __half hx = __float2half_rn(x), hy = __float2half_rn(y);
    __half lx = __float2half_rn(x - __half2float(hx));
    __half ly = __float2half_rn(y - __half2float(hy));
    __half2 h = __halves2half2(hx, hy);
    __half2 l = __halves2half2(lx, ly);
    hi = *reinterpret_cast<uint32_t*>(&h);
    lo = *reinterpret_cast<uint32_t*>(&l);
}

// ---------------- fused prep: cnt zero + dtype detect + both weight splits ----
// (byte-identical logic to the R14-passing version)
__global__ void k_prep_all(const int* __restrict__ e,
                           const float* __restrict__ W1,
                           const float* __restrict__ W2) {
    int i = blockIdx.x * blockDim.x + threadIdx.x;
    if (i < N_NODES) g_cnt[i] = 0;
    {
        int k2 = i >> 9, n = i & 511;
        float x = W1[(size_t)(2 * k2) * F_HID + n];
        float y = W1[(size_t)(2 * k2 + 1) * F_HID + n];
        splitf2(x, y, g_W1h[i], g_W1l[i]);
    }
    {
        int k2 = i >> 8, n = i & 255;
        float x = W2[(size_t)(2 * k2) * F_OUT + n];
        float y = W2[(size_t)(2 * k2 + 1) * F_OUT + n];
        splitf2(x, y, g_W2h[i], g_W2l[i]);
    }
    if (blockIdx.x == 0) {
        __shared__ int nz;
        if (threadIdx.x == 0) nz = 0;
        __syncthreads();
        for (int j = threadIdx.x; j < 1024; j += blockDim.x)
            if (e[2 * j + 1] != 0) atomicOr(&nz, 1);
        __syncthreads();
        if (threadIdx.x == 0) g_is64 = (nz == 0) ? 1 : 0;
    }
}

// ---------------- X -> half2-packed fp16 (separate kernel) ----------------
__global__ void k_xconv(const float2* __restrict__ x2, int n) {
    int i = blockIdx.x * blockDim.x + threadIdx.x;
    if (i >= n) return;
    float2 v = x2[i];
    __half2 hv = __floats2half2_rn(v.x, v.y);
    g_Xh[i] = *reinterpret_cast<uint32_t*>(&hv);
}

__global__ void k_fill(const void* __restrict__ e, int E) {
    int i = blockIdx.x * blockDim.x + threadIdx.x;
    if (i >= E) return;
    int is64 = g_is64;
    int s = load_idx(e, i, is64);
    int d = load_idx(e, (long long)E + i, is64);
    int slot = atomicAdd(&g_cnt[d], 1);
    if (slot < ELL) g_esrc[(size_t)d * ELL + slot] = s;
}

// ---------------- common: accumulate 8 features from one half2x4 row chunk ----
__device__ __forceinline__ void acc8(float* a, float nr, uint4 w) {
    float2 v;
    v = __half22float2(*(const __half2*)&w.x); a[0] += nr * v.x; a[1] += nr * v.y;
    v = __half22float2(*(const __half2*)&w.y); a[2] += nr * v.x; a[3] += nr * v.y;
    v = __half22float2(*(const __half2*)&w.z); a[4] += nr * v.x; a[5] += nr * v.y;
    v = __half22float2(*(const __half2*)&w.w); a[6] += nr * v.x; a[7] += nr * v.y;
}

// ---------------- ELL gather 1: fp16 X in (uint4-wide) -> split fp16 P1 (A layout) ----
__global__ void __launch_bounds__(256) k_gather1(const uint4* __restrict__ Xh4,
                                                 uint32_t* __restrict__ outh,
                                                 uint32_t* __restrict__ outl) {
    int d    = (int)((blockIdx.x * blockDim.x + threadIdx.x) >> 5);
    int lane = threadIdx.x & 31;
    if (d >= N_NODES) return;

    int cnt = min(g_cnt[d], ELL);
    float iv = rsqrtf((float)(g_cnt[d] + 1));
    float s2 = iv * iv;

    float a[8];
    {
        uint4 w = Xh4[(size_t)d * 32 + lane];
        float2 v;
        v = __half22float2(*(const __half2*)&w.x); a[0] = s2 * v.x; a[1] = s2 * v.y;
        v = __half22float2(*(const __half2*)&w.y); a[2] = s2 * v.x; a[3] = s2 * v.y;
        v = __half22float2(*(const __half2*)&w.z); a[4] = s2 * v.x; a[5] = s2 * v.y;
        v = __half22float2(*(const __half2*)&w.w); a[6] = s2 * v.x; a[7] = s2 * v.y;
    }

    const int* bucket = g_esrc + (size_t)d * ELL;
    for (int j0 = 0; j0 < cnt; j0 += 32) {
        int myj = j0 + lane;
        int   sl = (myj < cnt) ? bucket[myj] : 0;
        float nl = (myj < cnt) ? rsqrtf((float)(g_cnt[sl] + 1)) * iv : 0.f;
        int c = min(32, cnt - j0);
        int t = 0;
        for (; t + 4 <= c; t += 4) {
            int   si0 = __shfl_sync(0xFFFFFFFFu, sl, t);
            int   si1 = __shfl_sync(0xFFFFFFFFu, sl, t + 1);
            int   si2 = __shfl_sync(0xFFFFFFFFu, sl, t + 2);
            int   si3 = __shfl_sync(0xFFFFFFFFu, sl, t + 3);
            float n0 = __shfl_sync(0xFFFFFFFFu, nl, t);
            float n1 = __shfl_sync(0xFFFFFFFFu, nl, t + 1);
            float n2 = __shfl_sync(0xFFFFFFFFu, nl, t + 2);
            float n3 = __shfl_sync(0xFFFFFFFFu, nl, t + 3);
            uint4 w0 = Xh4[(size_t)si0 * 32 + lane];
            uint4 w1 = Xh4[(size_t)si1 * 32 + lane];
            uint4 w2 = Xh4[(size_t)si2 * 32 + lane];
            uint4 w3 = Xh4[(size_t)si3 * 32 + lane];
            acc8(a, n0, w0);
            acc8(a, n1, w1);
            acc8(a, n2, w2);
            acc8(a, n3, w3);
        }
        for (; t < c; t++) {
            int   si = __shfl_sync(0xFFFFFFFFu, sl, t);
            float nr = __shfl_sync(0xFFFFFFFFu, nl, t);
            uint4 w = Xh4[(size_t)si * 32 + lane];
            acc8(a, nr, w);
        }
    }

    // features 8*lane..8*lane+7 -> k2 = 4*lane + j
#pragma unroll
    for (int j = 0; j < 4; j++) {
        uint32_t h, l;
        splitf2(a[2 * j], a[2 * j + 1], h, l);
        size_t w = (size_t)(4 * lane + j) * MPAD + d;
        outh[w] = h;
        outl[w] = l;
    }
}

// ---------------- ELL gather 2: half2 T in (uint4-wide) -> fp32 out (+bias) ----------
__global__ void __launch_bounds__(256) k_gather2(const uint4* __restrict__ Th4,
                                                 float4* __restrict__ out4,
                                                 const float4* __restrict__ bias4) {
    int d    = (int)((blockIdx.x * blockDim.x + threadIdx.x) >> 5);
    int lane = threadIdx.x & 31;
    if (d >= N_NODES) return;

    int cnt = min(g_cnt[d], ELL);
    float iv = rsqrtf((float)(g_cnt[d] + 1));
    float s2 = iv * iv;

    float a[8];
    {
        uint4 w = Th4[(size_t)d * 32 + lane];
        float2 v;
        v = __half22float2(*(const __half2*)&w.x); a[0] = s2 * v.x; a[1] = s2 * v.y;
        v = __half22float2(*(const __half2*)&w.y); a[2] = s2 * v.x; a[3] = s2 * v.y;
        v = __half22float2(*(const __half2*)&w.z); a[4] = s2 * v.x; a[5] = s2 * v.y;
        v = __half22float2(*(const __half2*)&w.w); a[6] = s2 * v.x; a[7] = s2 * v.y;
        float4 b0 = bias4[lane * 2], b1 = bias4[lane * 2 + 1];
        a[0] += b0.x; a[1] += b0.y; a[2] += b0.z; a[3] += b0.w;
        a[4] += b1.x; a[5] += b1.y; a[6] += b1.z; a[7] += b1.w;
    }

    const int* bucket = g_esrc + (size_t)d * ELL;
    for (int j0 = 0; j0 < cnt; j0 += 32) {
        int myj = j0 + lane;
        int   sl = (myj < cnt) ? bucket[myj] : 0;
        float nl = (myj < cnt) ? rsqrtf((float)(g_cnt[sl] + 1)) * iv : 0.f;
        int c = min(32, cnt - j0);
        int t = 0;
        for (; t + 4 <= c; t += 4) {
            int   si0 = __shfl_sync(0xFFFFFFFFu, sl, t);
            int   si1 = __shfl_sync(0xFFFFFFFFu, sl, t + 1);
            int   si2 = __shfl_sync(0xFFFFFFFFu, sl, t + 2);
            int   si3 = __shfl_sync(0xFFFFFFFFu, sl, t + 3);
            float n0 = __shfl_sync(0xFFFFFFFFu, nl, t);
            float n1 = __shfl_sync(0xFFFFFFFFu, nl, t + 1);
            float n2 = __shfl_sync(0xFFFFFFFFu, nl, t + 2);
            float n3 = __shfl_sync(0xFFFFFFFFu, nl, t + 3);
            uint4 w0 = Th4[(size_t)si0 * 32 + lane];
            uint4 w1 = Th4[(size_t)si1 * 32 + lane];
            uint4 w2 = Th4[(size_t)si2 * 32 + lane];
            uint4 w3 = Th4[(size_t)si3 * 32 + lane];
            acc8(a, n0, w0);
            acc8(a, n1, w1);
            acc8(a, n2, w2);
            acc8(a, n3, w3);
        }
        for (; t < c; t++) {
            int   si = __shfl_sync(0xFFFFFFFFu, sl, t);
            float nr = __shfl_sync(0xFFFFFFFFu, nl, t);
            uint4 w = Th4[(size_t)si * 32 + lane];
            acc8(a, nr, w);
        }
    }

    float4* o = out4 + (size_t)d * 64;
    o[lane * 2]     = make_float4(a[0], a[1], a[2], a[3]);
    o[lane * 2 + 1] = make_float4(a[4], a[5], a[6], a[7]);
}

// ---------------- 3xFP16 GEMM (R10 config: BK=16, static smem) ----------------
__device__ __forceinline__ void mma_f16(float* d, const uint32_t* a, const uint32_t* b) {
    asm volatile(
        "mma.sync.aligned.m16n8k16.row.col.f32.f16.f16.f32 "
        "{%0,%1,%2,%3}, {%4,%5,%6,%7}, {%8,%9}, {%0,%1,%2,%3};"
        : "+f"(d[0]), "+f"(d[1]), "+f"(d[2]), "+f"(d[3])
        : "r"(a[0]), "r"(a[1]), "r"(a[2]), "r"(a[3]), "r"(b[0]), "r"(b[1]));
}

__device__ __forceinline__ void cp16(void* sd, const void* g) {
    uint32_t d;
    asm("{ .reg .u64 t; cvta.to.shared.u64 t, %1; cvt.u32.u64 %0, t; }" : "=r"(d) : "l"(sd));
    asm volatile("cp.async.cg.shared.global [%0], [%1], 16;\n" :: "r"(d), "l"(g));
}

#define BM 128
#define BN 128
#define SROW 136

// out_mode: 1 = split hi/lo (A layout, for H1), 2 = half2 hi only (row-major, for T)
__global__ void __launch_bounds__(256) gemm3xf16(const uint32_t* __restrict__ Ah,
                                                 const uint32_t* __restrict__ Al,
                                                 const uint32_t* __restrict__ Bh,
                                                 const uint32_t* __restrict__ Bl,
                                                 const float* __restrict__ bias,
                                                 uint32_t* __restrict__ Ch,
                                                 uint32_t* __restrict__ Cl,
                                                 int M, int N, int K2, int relu, int out_mode) {
    __shared__ uint32_t As_h[2][8][SROW], As_l[2][8][SROW];
    __shared__ uint32_t Bs_h[2][8][SROW], Bs_l[2][8][SROW];

    const int tid  = threadIdx.x;
    const int lane = tid & 31;
    const int warp = tid >> 5;
    const int g = lane >> 2;
    const int t = lane & 3;

    const int bm0 = blockIdx.x * BM;
    const int bn0 = blockIdx.y * BN;
    const int warp_m = warp & 3;
    const int warp_n = warp >> 2;

    float acc[2][8][4];
#pragma unroll
    for (int mt = 0; mt < 2; mt++)
#pragma unroll
        for (int nt = 0; nt < 8; nt++)
#pragma unroll
            for (int i = 0; i < 4; i++) acc[mt][nt][i] = 0.0f;

    const int lrow = tid >> 5;
    const int lch  = (tid & 31) * 4;

    auto load_tile = [&](int buf, int k20) {
        const size_t ar = (size_t)(k20 + lrow) * MPAD + bm0 + lch;
        const size_t br = (size_t)(k20 + lrow) * N    + bn0 + lch;
        cp16(&As_h[buf][lrow][lch], Ah + ar);
        cp16(&As_l[buf][lrow][lch], Al + ar);
        cp16(&Bs_h[buf][lrow][lch], Bh + br);
        cp16(&Bs_l[buf][lrow][lch], Bl + br);
        asm volatile("cp.async.commit_group;\n");
    };

    load_tile(0, 0);
    const int nk = K2 / 8;

    for (int ki = 0; ki < nk; ki++) {
        asm volatile("cp.async.wait_group 0;\n");
        __syncthreads();
        const int cur = ki & 1;
        if (ki + 1 < nk) load_tile((ki + 1) & 1, (ki + 1) * 8);

        uint32_t ah[2][4], al[2][4];
#pragma unroll
        for (int mt = 0; mt < 2; mt++) {
            int r = warp_m * 32 + mt * 16 + g;
            ah[mt][0] = As_h[cur][t][r];         al[mt][0] = As_l[cur][t][r];
            ah[mt][1] = As_h[cur][t][r + 8];     al[mt][1] = As_l[cur][t][r + 8];
            ah[mt][2] = As_h[cur][t + 4][r];     al[mt][2] = As_l[cur][t + 4][r];
            ah[mt][3] = As_h[cur][t + 4][r + 8]; al[mt][3] = As_l[cur][t + 4][r + 8];
        }
#pragma unroll
        for (int nt = 0; nt < 8; nt++) {
            int c = warp_n * 64 + nt * 8 + g;
            uint32_t bh[2], bl[2];
            bh[0] = Bs_h[cur][t][c];     bh[1] = Bs_h[cur][t + 4][c];
            bl[0] = Bs_l[cur][t][c];     bl[1] = Bs_l[cur][t + 4][c];
#pragma unroll
            for (int mt = 0; mt < 2; mt++) {
                mma_f16(acc[mt][nt], ah[mt], bh);
                mma_f16(acc[mt][nt], al[mt], bh);
                mma_f16(acc[mt][nt], ah[mt], bl);
            }
        }
    }

    // ---- epilogue ----
#pragma unroll
    for (int mt = 0; mt < 2; mt++) {
        int r0 = bm0 + warp_m * 32 + mt * 16 + g;
#pragma unroll
        for (int nt = 0; nt < 8; nt++) {
            int cc = bn0 + warp_n * 64 + nt * 8 + 2 * t;
            float2 v0, v1;
            v0.x = acc[mt][nt][0]; v0.y = acc[mt][nt][1];
            v1.x = acc[mt][nt][2]; v1.y = acc[mt][nt][3];
            if (bias) {
                float bx = bias[cc], by = bias[cc + 1];
                v0.x += bx; v0.y += by;
                v1.x += bx; v1.y += by;
            }
            if (relu) {
                v0.x = fmaxf(v0.x, 0.f); v0.y = fmaxf(v0.y, 0.f);
                v1.x = fmaxf(v1.x, 0.f); v1.y = fmaxf(v1.y, 0.f);
            }
            if (out_mode == 1) {
                size_t w = (size_t)(cc >> 1) * MPAD;
                uint32_t h, l;
                if (r0 < M)     { splitf2(v0.x, v0.y, h, l); Ch[w + r0] = h;     Cl[w + r0] = l; }
                if (r0 + 8 < M) { splitf2(v1.x, v1.y, h, l); Ch[w + r0 + 8] = h; Cl[w + r0 + 8] = l; }
            } else {
                if (r0 < M) {
                    __half2 hv = __floats2half2_rn(v0.x, v0.y);
                    Ch[(size_t)r0 * (N >> 1) + (cc >> 1)] = *reinterpret_cast<uint32_t*>(&hv);
                }
                if (r0 + 8 < M) {
                    __half2 hv = __floats2half2_rn(v1.x, v1.y);
                    Ch[(size_t)(r0 + 8) * (N >> 1) + (cc >> 1)] = *reinterpret_cast<uint32_t*>(&hv);
                }
            }
        }
    }
}

// ---------------- launch ----------------
extern "C" void kernel_launch(void* const* d_in, const int* in_sizes, int n_in,
                              void* d_out, int out_size) {
    const float* x  = (const float*)d_in[0];
    const void*  ei = d_in[1];
    const float* W1 = (const float*)d_in[2];
    const float* b1 = (const float*)d_in[3];
    const float* W2 = (const float*)d_in[4];
    const float* b2 = (const float*)d_in[5];
    float* out = (float*)d_out;

    int E = in_sizes[1] / 2;

    uint32_t *P1h, *P1l, *H1h, *H1l, *W1h, *W1l, *W2h, *W2l, *Th, *Xh;
    cudaGetSymbolAddress((void**)&P1h, g_P1h); cudaGetSymbolAddress((void**)&P1l, g_P1l);
    cudaGetSymbolAddress((void**)&H1h, g_H1h); cudaGetSymbolAddress((void**)&H1l, g_H1l);
    cudaGetSymbolAddress((void**)&W1h, g_W1h); cudaGetSymbolAddress((void**)&W1l, g_W1l);
    cudaGetSymbolAddress((void**)&W2h, g_W2h); cudaGetSymbolAddress((void**)&W2l, g_W2l);
    cudaGetSymbolAddress((void**)&Th,  g_Th);  cudaGetSymbolAddress((void**)&Xh,  g_Xh);

    const int TPB = 256;
    int edgeBlocks = (E + TPB - 1) / TPB;
    int gatherBlocks = (N_NODES * 32 + TPB - 1) / TPB;
    int mBlocks = (N_NODES + BM - 1) / BM;
    int xWords = N_NODES * (F_IN / 2);

    k_prep_all<<<256, TPB>>>((const int*)ei, W1, W2);
    k_xconv<<<(xWords + TPB - 1) / TPB, TPB>>>((const float2*)x, xWords);
    k_fill<<<edgeBlocks, TPB>>>(ei, E);
    k_gather1<<<gatherBlocks, TPB>>>((const uint4*)Xh, P1h, P1l);
    {
        dim3 grid(mBlocks, F_HID / BN);
        gemm3xf16<<<grid, TPB>>>(P1h, P1l, W1h, W1l, b1, H1h, H1l,
                                 N_NODES, F_HID, F_IN / 2, 1, 1);
    }
    {
        dim3 grid(mBlocks, F_OUT / BN);
        gemm3xf16<<<grid, TPB>>>(H1h, H1l, W2h, W2l, nullptr, Th, nullptr,
                                 N_NODES, F_OUT, F_HID / 2, 0, 2);
    }
    k_gather2<<<gatherBlocks, TPB>>>((const uint4*)Th, (float4*)out, (const float4*)b2);
}